// round 17
// baseline (speedup 1.0000x reference)
#include <cuda_runtime.h>
#include <cuda_bf16.h>
#include <cstdint>

#define NQ 32768          // B*H*W queries
#define KC 1024           // codebook entries
#define DD 256            // embedding dim
#define ZQ_ELEMS 8388608  // 32*256*32*32
#define CAP 32
#define EPS 1.0e-3f

// ---------------------------------------------------------------------------
// Device-global scratch (allocation-free rule)
// ---------------------------------------------------------------------------
__device__ float g_cnorm[KC];
__device__ float g_znorm[NQ];
__device__ int   g_idx[NQ];
__device__ float g_part[256];
__device__ int   g_cnt[NQ];
__device__ int   g_cand[NQ * CAP];
__device__ float g_zt[(size_t)NQ * DD];
__device__ __nv_bfloat16 g_cbh[KC * DD];
__device__ __nv_bfloat16 g_zh[(size_t)NQ * DD];

// ---------------------------------------------------------------------------
// PTX helpers (baseline ISA only: cp.async, ldmatrix, mma.sync — sm_80+)
// ---------------------------------------------------------------------------
__device__ __forceinline__ uint32_t smem_u32(const void* p) {
    uint32_t a;
    asm("{ .reg .u64 t; cvta.to.shared.u64 t, %1; cvt.u32.u64 %0, t; }"
        : "=r"(a) : "l"(p));
    return a;
}
__device__ __forceinline__ void cp_async16(uint32_t saddr, const void* g) {
    asm volatile("cp.async.cg.shared.global [%0], [%1], 16;"
                 :: "r"(saddr), "l"(g) : "memory");
}
#define CP_COMMIT() asm volatile("cp.async.commit_group;" ::: "memory")
#define CP_WAIT1()  asm volatile("cp.async.wait_group 1;" ::: "memory")
#define CP_WAIT0()  asm volatile("cp.async.wait_group 0;" ::: "memory")

__device__ __forceinline__ void ldsm4(uint32_t* r, uint32_t addr) {
    asm volatile("ldmatrix.sync.aligned.m8n8.x4.shared.b16 {%0,%1,%2,%3}, [%4];"
                 : "=r"(r[0]), "=r"(r[1]), "=r"(r[2]), "=r"(r[3]) : "r"(addr));
}
__device__ __forceinline__ void mma_bf16(float* d, const uint32_t* a,
                                         const uint32_t* b) {
    asm volatile(
        "mma.sync.aligned.m16n8k16.row.col.f32.bf16.bf16.f32 "
        "{%0,%1,%2,%3}, {%4,%5,%6,%7}, {%8,%9}, {%0,%1,%2,%3};"
        : "+f"(d[0]), "+f"(d[1]), "+f"(d[2]), "+f"(d[3])
        : "r"(a[0]), "r"(a[1]), "r"(a[2]), "r"(a[3]), "r"(b[0]), "r"(b[1]));
}

// ---------------------------------------------------------------------------
// Fused codebook prep: row norms (round-2 exact order) + bf16 conversion
// ---------------------------------------------------------------------------
__global__ void cnorm_cb_kernel(const float* __restrict__ cb) {
    int k = blockIdx.x * blockDim.x + threadIdx.x;
    const float* row = cb + (size_t)k * DD;
    __nv_bfloat16* dst = g_cbh + (size_t)k * DD;
    float s = 0.f;
    for (int d = 0; d < DD; ++d) {
        float v = row[d];
        dst[d] = __float2bfloat16(v);
        s = __fadd_rn(s, __fmul_rn(v, v));
    }
    g_cnorm[k] = s;
}

// ---------------------------------------------------------------------------
// Fused z prep: NCHW -> [query][d] fp32 + bf16 transpose AND query norms.
// Block = (b, 32-wide hw slice) x all 256 channels.  Norm summation is
// bit-identical to the round-2 passing kernel (two ascending 128-chains +
// one final fadd) -- this shape is load-bearing for the accepted rel_err.
// ---------------------------------------------------------------------------
__global__ __launch_bounds__(256) void prep_z_fused_kernel(const float* __restrict__ z) {
    __shared__ float tile[256 * 33];   // [c][hw], row stride 33
    __shared__ float red[64];
    const int t   = threadIdx.x;       // = channel c for the load phase
    const int b   = blockIdx.y;
    const int hw0 = blockIdx.x * 32;

    // load channel row t (32 floats, one 128B line) into smem
    {
        const float* src = z + ((size_t)(b * 256 + t)) * 1024 + hw0;
        #pragma unroll
        for (int u = 0; u < 8; ++u) {
            float4 v = *reinterpret_cast<const float4*>(src + u * 4);
            tile[t * 33 + u * 4 + 0] = v.x;
            tile[t * 33 + u * 4 + 1] = v.y;
            tile[t * 33 + u * 4 + 2] = v.z;
            tile[t * 33 + u * 4 + 3] = v.w;
        }
    }
    __syncthreads();

    // query norms: 2 threads per query, ascending-d 128-chains (round-2 exact)
    if (t < 64) {
        const int q = t & 31, half = t >> 5;
        float s = 0.f;
        #pragma unroll 4
        for (int d = 0; d < 128; ++d) {
            float v = tile[(half * 128 + d) * 33 + q];
            s = __fadd_rn(s, __fmul_rn(v, v));
        }
        red[t] = s;
    }
    __syncthreads();
    if (t < 32) {
        int n = b * 1024 + hw0 + t;
        g_znorm[n] = __fadd_rn(red[t], red[t + 32]);
        g_cnt[n] = 0;
    }

    // transposed outputs: thread = (qlocal, c-group); staggered u to avoid
    // smem bank conflicts (cidx % 32 distinct across the 8 c-groups)
    {
        const int qlocal = t >> 3;
        const int gidx   = t & 7;
        const size_t n   = (size_t)b * 1024 + hw0 + qlocal;
        float*         zt = g_zt + n * 256;
        __nv_bfloat16* zh = g_zh + n * 256;
        #pragma unroll
        for (int u = 0; u < 32; ++u) {
            int cidx = gidx * 32 + ((u + gidx * 4) & 31);
            float v = tile[cidx * 33 + qlocal];
            zt[cidx] = v;
            zh[cidx] = __float2bfloat16(v);
        }
    }
}

// ---------------------------------------------------------------------------
// SINGLE-PASS bf16 HMMA distance GEMM + candidate collection.
// Exact fp32 rerank decides the final index; GEMM only needs accuracy << EPS.
// CTA = 128 queries x 1024 codes, K = 256.  A resident (66KB, odd stride),
// B double-buffered 128x64 chunks (18KB each).  2 CTAs/SM.
// Epilogue transforms accumulators to scores IN PLACE (register relief).
// ---------------------------------------------------------------------------
#define A_ROWB   528
#define A_BYTES  (128 * A_ROWB)       // 67584
#define B_ROWB   144
#define B_STAGE  (128 * B_ROWB)       // 18432
#define DYN_SMEM (A_BYTES + 2 * B_STAGE)   // 104448

__global__ __launch_bounds__(256, 2) void hmma_argmin_kernel() {
    extern __shared__ __align__(16) char dsm[];
    __shared__ float cn_s[KC];
    __shared__ float zn_s[128];

    const int t    = threadIdx.x;
    const int lane = t & 31;
    const int warp = t >> 5;
    const int warp_m = warp >> 1;     // 0..3  (32 rows each)
    const int warp_n = warp & 1;      // 0..1  (64 cols each)
    const int q0   = blockIdx.x * 128;

    const uint32_t a_base = smem_u32(dsm);
    const uint32_t b_base = a_base + A_BYTES;

    for (int i = t; i < KC; i += 256) cn_s[i] = g_cnorm[i];
    if (t < 128) zn_s[t] = g_znorm[q0 + t];

    // ---- prologue: A (4096 x 16B) + B chunk 0, one cp.async group ----
    #pragma unroll 4
    for (int i = 0; i < 16; ++i) {
        int o = t + 256 * i;
        int row = o >> 5, u = o & 31;
        cp_async16(a_base + row * A_ROWB + u * 16,
                   g_zh + (size_t)(q0 + row) * 256 + u * 8);
    }
    #pragma unroll
    for (int i = 0; i < 4; ++i) {
        int o = t + 256 * i;
        int row = o >> 3, u = o & 7;
        cp_async16(b_base + row * B_ROWB + u * 16,
                   g_cbh + (size_t)row * 256 + u * 8);
    }
    CP_COMMIT();

    float acc[2][8][4];
    #pragma unroll
    for (int m = 0; m < 2; ++m)
        #pragma unroll
        for (int j = 0; j < 8; ++j)
            #pragma unroll
            for (int r = 0; r < 4; ++r) acc[m][j][r] = 0.f;

    float bestv[4] = {3.4e38f, 3.4e38f, 3.4e38f, 3.4e38f};

    // ldmatrix lane addressing (conflict-free: row strides are odd 16B units)
    const int a_ro = (lane & 7) + ((lane >> 3) & 1) * 8;
    const int a_lc = lane >> 4;
    const int b_ro = (lane & 7) + ((lane >> 4) & 1) * 8;
    const int b_lc = (lane >> 3) & 1;
    const uint32_t a_ptr0 = a_base + (warp_m * 32 + a_ro) * A_ROWB + a_lc * 16;
    const uint32_t b_ptr0 = b_base + (warp_n * 64 + b_ro) * B_ROWB + b_lc * 16;

    // 32 chunks: nt = gc/4 (code tile), c = gc%4 (64-K slice)
    for (int gc = 0; gc < 32; ++gc) {
        const int s  = gc & 1;
        const int nt = gc >> 2;
        const int c  = gc & 3;

        if (gc + 1 < 32) {
            const int nt2 = (gc + 1) >> 2, kc2 = (gc + 1) & 3;
            const uint32_t dst = b_base + (uint32_t)(s ^ 1) * B_STAGE;
            #pragma unroll
            for (int i = 0; i < 4; ++i) {
                int o = t + 256 * i;
                int row = o >> 3, u = o & 7;
                cp_async16(dst + row * B_ROWB + u * 16,
                           g_cbh + (size_t)(nt2 * 128 + row) * 256 + kc2 * 64 + u * 8);
            }
            CP_COMMIT();
            CP_WAIT1();
        } else {
            CP_WAIT0();
        }
        __syncthreads();

        const uint32_t ap = a_ptr0 + (uint32_t)c * 128u;   // 64 bf16 = 128B per kc
        const uint32_t bp = b_ptr0 + (uint32_t)s * B_STAGE;

        #pragma unroll
        for (int j = 0; j < 4; ++j) {
            uint32_t a0[4], a1[4];
            ldsm4(a0, ap + j * 32);
            ldsm4(a1, ap + 16 * A_ROWB + j * 32);
            #pragma unroll
            for (int q = 0; q < 4; ++q) {
                uint32_t bq[4];
                ldsm4(bq, bp + q * (16 * B_ROWB) + j * 32);
                mma_bf16(acc[0][2 * q + 0], a0, bq + 0);
                mma_bf16(acc[0][2 * q + 1], a0, bq + 2);
                mma_bf16(acc[1][2 * q + 0], a1, bq + 0);
                mma_bf16(acc[1][2 * q + 1], a1, bq + 2);
            }
        }

        // end-of-code-tile epilogue: in-place scores, best, collection
        if (c == 3) {
            #pragma unroll
            for (int m = 0; m < 2; ++m) {
                #pragma unroll
                for (int rh = 0; rh < 2; ++rh) {
                    const int sl = m * 2 + rh;
                    const float zn = zn_s[warp_m * 32 + m * 16 + rh * 8 + (lane >> 2)];
                    #pragma unroll
                    for (int jn = 0; jn < 8; ++jn) {
                        const int k0 = nt * 128 + warp_n * 64 + jn * 8 + (lane & 3) * 2;
                        acc[m][jn][rh * 2 + 0] =
                            __fadd_rn(__fadd_rn(zn, cn_s[k0]),
                                      __fmul_rn(-2.f, acc[m][jn][rh * 2 + 0]));
                        acc[m][jn][rh * 2 + 1] =
                            __fadd_rn(__fadd_rn(zn, cn_s[k0 + 1]),
                                      __fmul_rn(-2.f, acc[m][jn][rh * 2 + 1]));
                    }
                    #pragma unroll
                    for (int jn = 0; jn < 8; ++jn) {
                        if (acc[m][jn][rh * 2 + 0] < bestv[sl]) bestv[sl] = acc[m][jn][rh * 2 + 0];
                        if (acc[m][jn][rh * 2 + 1] < bestv[sl]) bestv[sl] = acc[m][jn][rh * 2 + 1];
                    }
                    float qm = bestv[sl];
                    qm = fminf(qm, __shfl_xor_sync(0xffffffffu, qm, 1));
                    qm = fminf(qm, __shfl_xor_sync(0xffffffffu, qm, 2));
                    const float thr = qm + EPS;
                    const int rowg = q0 + warp_m * 32 + m * 16 + rh * 8 + (lane >> 2);
                    #pragma unroll
                    for (int jn = 0; jn < 8; ++jn) {
                        #pragma unroll
                        for (int i = 0; i < 2; ++i) {
                            if (acc[m][jn][rh * 2 + i] < thr) {
                                int k = nt * 128 + warp_n * 64 + jn * 8
                                      + (lane & 3) * 2 + i;
                                int pos = atomicAdd(&g_cnt[rowg], 1);
                                if (pos < CAP) g_cand[rowg * CAP + pos] = k;
                            }
                        }
                    }
                }
            }
            #pragma unroll
            for (int m = 0; m < 2; ++m)
                #pragma unroll
                for (int j = 0; j < 8; ++j)
                    #pragma unroll
                    for (int r = 0; r < 4; ++r) acc[m][j][r] = 0.f;
        }
        __syncthreads();   // all warps done with stage s before it is refilled
    }
}

// ---------------------------------------------------------------------------
// Exact fp32 re-rank of collected candidates (round-2 arithmetic, bit-matched)
// ---------------------------------------------------------------------------
__global__ __launch_bounds__(256) void rerank_kernel(const float* __restrict__ cb) {
    const int warp = threadIdx.x >> 5, lane = threadIdx.x & 31;
    const int q = blockIdx.x * 8 + warp;
    const int cnt = g_cnt[q];

    if (cnt == 1) {
        if (lane == 0) g_idx[q] = g_cand[q * CAP];
        return;
    }

    const float zn = g_znorm[q];
    const float* zr = g_zt + (size_t)q * DD;
    float bv = 3.4e38f;
    int   bi = 0x7FFFFFFF;

    if (cnt <= CAP) {
        if (lane < cnt) {
            int k = g_cand[q * CAP + lane];
            const float* cr = cb + (size_t)k * DD;
            float acc = 0.f;
            for (int d = 0; d < DD; ++d) acc = fmaf(zr[d], cr[d], acc);
            bv = __fadd_rn(__fadd_rn(zn, g_cnorm[k]), __fmul_rn(-2.f, acc));
            bi = k;
        }
    } else {                              // overflow fallback: full exact scan
        for (int k = lane; k < KC; k += 32) {
            const float* cr = cb + (size_t)k * DD;
            float acc = 0.f;
            for (int d = 0; d < DD; ++d) acc = fmaf(zr[d], cr[d], acc);
            float sc = __fadd_rn(__fadd_rn(zn, g_cnorm[k]), __fmul_rn(-2.f, acc));
            if (sc < bv || (sc == bv && k < bi)) { bv = sc; bi = k; }
        }
    }
    #pragma unroll
    for (int off = 16; off >= 1; off >>= 1) {
        float v2 = __shfl_xor_sync(0xffffffffu, bv, off);
        int   i2 = __shfl_xor_sync(0xffffffffu, bi, off);
        if (v2 < bv || (v2 == bv && i2 < bi)) { bv = v2; bi = i2; }
    }
    if (lane == 0) g_idx[q] = bi;
}

// ---------------------------------------------------------------------------
// Gather z_q (NCHW via smem transpose) + loss partials
// ---------------------------------------------------------------------------
__global__ __launch_bounds__(256) void gather_kernel(
        const float* __restrict__ z, const float* __restrict__ cb,
        float* __restrict__ out_zq, float* __restrict__ out_idxf) {
    __shared__ float tile[32][129];
    __shared__ int   idx_s[128];
    __shared__ float red[256];

    const int t   = threadIdx.x;
    const int n0  = blockIdx.x * 128;
    const int b   = n0 >> 10;
    const int hw0 = n0 & 1023;

    if (t < 128) {
        int id = g_idx[n0 + t];
        idx_s[t] = id;
        out_idxf[n0 + t] = (float)id;
    }
    __syncthreads();

    float lsum = 0.f;
    for (int c0 = 0; c0 < DD; c0 += 32) {
        {
            int q = t >> 1, part = t & 1;
            const float* src = cb + (size_t)idx_s[q] * DD + c0 + part * 16;
            #pragma unroll
            for (int u = 0; u < 4; ++u) {
                float4 v = *reinterpret_cast<const float4*>(src + u * 4);
                int cc = part * 16 + u * 4;
                tile[cc + 0][q] = v.x; tile[cc + 1][q] = v.y;
                tile[cc + 2][q] = v.z; tile[cc + 3][q] = v.w;
            }
        }
        __syncthreads();
        #pragma unroll
        for (int i = 0; i < 16; ++i) {
            int lin = t + 256 * i;
            int cc  = lin >> 7;
            int q   = lin & 127;
            size_t gaddr = ((size_t)(b * 256 + c0 + cc)) * 1024 + hw0 + q;
            float v  = tile[cc][q];
            out_zq[gaddr] = v;
            float dv = v - z[gaddr];
            lsum = fmaf(dv, dv, lsum);
        }
        __syncthreads();
    }

    red[t] = lsum;
    __syncthreads();
    for (int s = 128; s > 0; s >>= 1) {
        if (t < s) red[t] += red[t + s];
        __syncthreads();
    }
    if (t == 0) g_part[blockIdx.x] = red[0];
}

__global__ void loss_kernel(float* __restrict__ out_loss) {
    __shared__ float red[256];
    int t = threadIdx.x;
    red[t] = g_part[t];
    __syncthreads();
    for (int s = 128; s > 0; s >>= 1) {
        if (t < s) red[t] += red[t + s];
        __syncthreads();
    }
    if (t == 0) out_loss[0] = 1.25f * red[0] / (float)ZQ_ELEMS;
}

// ---------------------------------------------------------------------------
extern "C" void kernel_launch(void* const* d_in, const int* in_sizes, int n_in,
                              void* d_out, int out_size) {
    const float* z  = (const float*)d_in[0];   // [32,256,32,32]
    const float* cb = (const float*)d_in[1];   // [1024,256]
    float* out      = (float*)d_out;
    float* out_zq   = out;
    float* out_loss = out + ZQ_ELEMS;
    float* out_idxf = out + ZQ_ELEMS + 1;

    cudaFuncSetAttribute(hmma_argmin_kernel,
                         cudaFuncAttributeMaxDynamicSharedMemorySize, DYN_SMEM);

    cnorm_cb_kernel<<<4, 256>>>(cb);
    prep_z_fused_kernel<<<dim3(32, 32), 256>>>(z);
    hmma_argmin_kernel<<<NQ / 128, 256, DYN_SMEM>>>();
    rerank_kernel<<<NQ / 8, 256>>>(cb);
    gather_kernel<<<NQ / 128, 256>>>(z, cb, out_zq, out_idxf);
    loss_kernel<<<1, 256>>>(out_loss);
}